// round 13
// baseline (speedup 1.0000x reference)
#include <cuda_runtime.h>

// DfOp: complex order-5 causal FIR on first 96 freq bins, copy the rest.
// spec: (B=8, T=3000, F=481, 2) f32 ; coef: (B=8, T=3000, 96, 10) f32
//
// R13: uniform-warp variant of the champion. One block per row, 96 threads;
// EVERY thread does: 1 DF bin (5x coef + 5x tap LDG.64, front-batched) plus
// 2 copy float4 items (+ thread 0 the tail float2). All warps identical ->
// no early-idle copy warps; 21 blocks/SM = 98% occupancy (vs 77-79%).
// All alignment branches remain block-uniform (row parity).

#define T_DIM 3000
#define F_DIM 481
#define NDF   96
#define NO    5

__global__ __launch_bounds__(96, 21) void df_kernel(
    const float* __restrict__ spec,
    const float* __restrict__ coef,
    float* __restrict__ out)
{
    const int bt = blockIdx.x;          // row = b*T + t
    const int t  = bt % T_DIM;

    const float2* __restrict__ spec2 = reinterpret_cast<const float2*>(spec);
    const float4* __restrict__ spec4 = reinterpret_cast<const float4*>(spec);
    float2* __restrict__ out2 = reinterpret_cast<float2*>(out);
    float4* __restrict__ out4 = reinterpret_cast<float4*>(out);

    const size_t row = (size_t)bt * F_DIM;     // float2 units
    const int tid = threadIdx.x;               // 0..95
    const bool odd = (bt & 1);
    const size_t v4base = (row + NDF + (odd ? 1 : 0)) >> 1;

    // ---------- front-batched loads: 5 coef + 5 taps + 2 copy float4 ----------
    const int f = tid;
    const float2* __restrict__ c2 =
        reinterpret_cast<const float2*>(coef + ((size_t)bt * NDF + f) * (2 * NO));
    const float2 p0 = c2[0];
    const float2 p1 = c2[1];
    const float2 p2 = c2[2];
    const float2 p3 = c2[3];
    const float2 p4 = c2[4];

    float2 x[NO];
    if (t >= NO - 1) {
        #pragma unroll
        for (int k = 0; k < NO; ++k)
            x[k] = spec2[((size_t)(bt - (NO - 1) + k)) * F_DIM + f];
    } else {
        #pragma unroll
        for (int k = 0; k < NO; ++k) {
            x[k] = make_float2(0.f, 0.f);
            if (t - (NO - 1) + k >= 0)
                x[k] = spec2[((size_t)(bt - (NO - 1) + k)) * F_DIM + f];
        }
    }

    // copy loads (2 float4 per thread: items tid and tid+96 of 192)
    const size_t i4a = v4base + tid;
    const size_t i4b = v4base + NDF + tid;
    const float4 ca = spec4[i4a];
    const float4 cb = spec4[i4b];
    float2 tail;
    const size_t i2t = row + (odd ? NDF : (F_DIM - 1));
    if (tid == 0) tail = spec2[i2t];

    // ---------------- compute ----------------
    const float cr[NO] = {p0.x, p0.y, p1.x, p1.y, p2.x};
    const float ci[NO] = {p2.y, p3.x, p3.y, p4.x, p4.y};

    float fr = 0.f, fi = 0.f;
    #pragma unroll
    for (int k = 0; k < NO; ++k) {
        fr += x[k].x * cr[k] - x[k].y * ci[k];
        fi += x[k].x * ci[k] + x[k].y * cr[k];
    }

    // ---------------- stores ----------------
    out2[row + f] = make_float2(fr, fi);
    out4[i4a] = ca;
    out4[i4b] = cb;
    if (tid == 0) out2[i2t] = tail;
}

extern "C" void kernel_launch(void* const* d_in, const int* in_sizes, int n_in,
                              void* d_out, int out_size)
{
    const float* spec = (const float*)d_in[0];
    const float* coef = (const float*)d_in[1];
    float* out        = (float*)d_out;

    df_kernel<<<8 * T_DIM, 96>>>(spec, coef, out);
}